// round 11
// baseline (speedup 1.0000x reference)
#include <cuda_runtime.h>
#include <cstdint>
#include <climits>

#define T_STEPS 200
#define B_SZ    256
#define IN_SZ   784
#define N_SZ    400
#define N_HALF  200

#define ALPHA      0.9f
#define BETA       0.8f
#define THRESH     1.0f
#define BETA_PLUS  0.9f
#define BETA_MINUS 0.9f
#define A_PLUS     1e-3f
#define A_MINUS    1e-3f
#define LI_STR     0.1f

// ---------------- persistent device state ----------------
__device__ float g_Wt[IN_SZ * N_SZ];       // W transposed: Wt[k*N + n] = W[n, k]
__device__ float g_syn[B_SZ * N_SZ];
__device__ float g_mem[B_SZ * N_SZ];
__device__ float g_post[B_SZ * N_SZ];
__device__ float g_trT[IN_SZ * B_SZ];      // TRANSPOSED pre-trace: trT[k*B + b] = tr_t[b,k]
__device__ int   g_win[T_STEPS * B_SZ];    // per (t,b) winner via atomicMin
__device__ int   g_flag[T_STEPS];
__device__ int   g_imgcnt[IN_SZ];
__device__ __align__(16) int g_imglist[IN_SZ * B_SZ];  // per input k: batch rows with img=1
__device__ __align__(16) unsigned g_spkmask[N_SZ * 8]; // per neuron n: 256-bit spike mask over b

// ---------------- init ----------------
__global__ void k_init(const float* __restrict__ W) {
    int idx = blockIdx.x * blockDim.x + threadIdx.x;
    int stride = gridDim.x * blockDim.x;
    for (int j = idx; j < IN_SZ * N_SZ; j += stride) {
        int k = j / N_SZ, n = j % N_SZ;
        g_Wt[j] = W[n * IN_SZ + k];
    }
    for (int j = idx; j < B_SZ * N_SZ; j += stride) {
        g_syn[j] = 0.f; g_mem[j] = 0.f; g_post[j] = 0.f;
    }
    for (int j = idx; j < IN_SZ * B_SZ; j += stride) g_trT[j] = 0.f;
    for (int j = idx; j < T_STEPS * B_SZ; j += stride) g_win[j] = INT_MAX;
    for (int j = idx; j < T_STEPS; j += stride) g_flag[j] = 0;
}

// ---------------- K1: neuron update, grid (B, 2): one block per (batch row, n-half) ----
__global__ void __launch_bounds__(256) k_neuron(const float* __restrict__ img, int t,
                                                float* __restrict__ memrec,
                                                float* __restrict__ spkrec) {
    int b = blockIdx.x;
    int half = blockIdx.y;
    int tid = threadIdx.x;

    __shared__ float simg[IN_SZ];
    __shared__ int   s_act[IN_SZ];
    __shared__ int   s_cnt;
    __shared__ int   s_win;
    __shared__ int   s_any;

    const float* imgt = img + ((size_t)t * B_SZ + b) * IN_SZ;
    for (int k = tid; k < IN_SZ; k += 256) simg[k] = imgt[k];
    if (tid == 0) { s_win = INT_MAX; s_any = 0; }
    __syncthreads();

    // warp 0: order-preserving compaction of active input indices
    if (tid < 32) {
        int base = 0;
        for (int c = 0; c < (IN_SZ + 31) / 32; c++) {
            int k = c * 32 + tid;
            bool act = (k < IN_SZ) && (simg[k] != 0.0f);
            unsigned m = __ballot_sync(0xffffffffu, act);
            if (act) s_act[base + __popc(m & ((1u << tid) - 1u))] = k;
            base += __popc(m);
        }
        if (tid == 0) s_cnt = base;
    }
    __syncthreads();

    int cnt = s_cnt;
    if (tid < N_HALF) {
        int n = half * N_HALF + tid;
        // hoist state loads so they overlap the gather
        float m = g_mem[b * N_SZ + n];
        float s = g_syn[b * N_SZ + n];

        float cur = 0.f;
        for (int i = 0; i < cnt; i++) cur += g_Wt[s_act[i] * N_SZ + n];

        float reset = (m > THRESH) ? 1.0f : 0.0f;
        s = ALPHA * s + cur;
        m = BETA * m + s - reset * THRESH;
        float spk = (m > THRESH) ? 1.0f : 0.0f;

        size_t rec = ((size_t)t * B_SZ + b) * N_SZ + n;
        memrec[rec] = m;
        spkrec[rec] = spk;
        g_syn[b * N_SZ + n] = s;
        g_mem[b * N_SZ + n] = m;

        if (spk != 0.f) { atomicMin(&s_win, n); s_any = 1; }
    }
    __syncthreads();
    if (tid == 0) {
        if (s_win != INT_MAX) atomicMin(&g_win[t * B_SZ + b], s_win);
        if (s_any) atomicOr(&g_flag[t], 1);
    }
}

// ---------------- K2: prep ----------------
// Blocks [0,98):    img-active lists per k (8 warps x 98 = 784)
// Blocks [98,148):  spike bitmasks per n (8 warps x 50 = 400)
// Blocks [148,548): element-wise LI + post-trace update over [B,N]
// Blocks [548,748): transposed trace update trT = bp*trT + img[t-1]^T (32x32 tiles)
#define PREP_IMG  98
#define PREP_MSK  148
#define PREP_LI   548
#define PREP_TOT  748
__global__ void __launch_bounds__(256) k_prep(const float* __restrict__ img,
                                              const float* __restrict__ spkrec, int t) {
    int bid = blockIdx.x;
    int tid = threadIdx.x;

    if (bid < PREP_IMG) {
        int w = tid >> 5, lane = tid & 31;
        int k = bid * 8 + w;
        const float* imgt = img + (size_t)t * B_SZ * IN_SZ;
        int base = 0;
        for (int c = 0; c < B_SZ / 32; c++) {
            int b = c * 32 + lane;
            bool a = imgt[(size_t)b * IN_SZ + k] != 0.0f;
            unsigned m = __ballot_sync(0xffffffffu, a);
            if (a) g_imglist[k * B_SZ + base + __popc(m & ((1u << lane) - 1u))] = b;
            base += __popc(m);
        }
        if (lane == 0) g_imgcnt[k] = base;
    } else if (bid < PREP_MSK) {
        int w = tid >> 5, lane = tid & 31;
        int n = (bid - PREP_IMG) * 8 + w;
        const float* spkt = spkrec + (size_t)t * B_SZ * N_SZ;
        for (int c = 0; c < B_SZ / 32; c++) {
            int b = c * 32 + lane;
            bool a = spkt[b * N_SZ + n] != 0.0f;
            unsigned m = __ballot_sync(0xffffffffu, a);
            if (lane == 0) g_spkmask[n * 8 + c] = m;
        }
    } else if (bid < PREP_LI) {
        int idx = (bid - PREP_MSK) * 256 + tid;
        if (idx < B_SZ * N_SZ) {
            int b = idx / N_SZ, n = idx % N_SZ;
            float spk = spkrec[(size_t)t * B_SZ * N_SZ + idx];
            if (g_flag[t]) {
                int win = g_win[t * B_SZ + b];
                if (win == INT_MAX) win = 0;   // argmax of all-zeros row = 0
                if (n != win) g_syn[idx] -= LI_STR;
            }
            g_post[idx] = BETA_MINUS * g_post[idx] + spk;
        }
    } else {
        if (t == 0) return;   // trT stays zero for step 0
        int d = bid - PREP_LI;             // 0..199
        int kt = d % 25, bt = d / 25;      // 25 k-tiles x 8 b-tiles
        int k0 = kt * 32, b0 = bt * 32;
        __shared__ float s[32][33];
        int tx = tid & 31, ty = tid >> 5;  // ty 0..7
        const float* imgp = img + (size_t)(t - 1) * B_SZ * IN_SZ;
#pragma unroll
        for (int r = 0; r < 4; r++) {
            int bl = ty + r * 8;           // local b
            int k = k0 + tx;
            s[bl][tx] = (k < IN_SZ) ? imgp[(size_t)(b0 + bl) * IN_SZ + k] : 0.f;
        }
        __syncthreads();
#pragma unroll
        for (int r = 0; r < 4; r++) {
            int kl = ty + r * 8;           // local k
            int k = k0 + kl;
            if (k < IN_SZ) {
                int j = k * B_SZ + b0 + tx;
                g_trT[j] = BETA_PLUS * g_trT[j] + s[tx][kl];
            }
        }
    }
}

// ---------------- K3: fused STDP update, grid (IN, 2): one block per (k, n-half) ----
// Wt[k,n] = clip(Wt[k,n] + A_PLUS * sum_{b: spk[b,n]=1} trT[k,b]
//                        - A_MINUS * sum_{b: img[b,k]=1} post[b,n], 0, 1)
__global__ void __launch_bounds__(256) k_stdp() {
    int k = blockIdx.x;
    int half = blockIdx.y;
    int tid = threadIdx.x;
    int n = half * N_HALF + tid;

    __shared__ float s_tr[B_SZ];
    __shared__ float s_ps[8];      // per-32-chunk partial sums of s_tr

    // issue all independent loads up front
    uint4 mA = make_uint4(0, 0, 0, 0), mB = make_uint4(0, 0, 0, 0);
    float wv = 0.f;
    if (tid < N_HALF) {
        const uint4* mp = reinterpret_cast<const uint4*>(&g_spkmask[n * 8]);
        mA = mp[0]; mB = mp[1];
        wv = g_Wt[k * N_SZ + n];
    }
    int icnt = g_imgcnt[k];        // warp-uniform broadcast load, no barrier needed

    // all 8 warps: load trace row + deterministic per-chunk reduction
    {
        float trv = g_trT[k * B_SZ + tid];
        s_tr[tid] = trv;
        float v = trv;
#pragma unroll
        for (int off = 16; off > 0; off >>= 1)
            v += __shfl_xor_sync(0xffffffffu, v, off);
        if ((tid & 31) == 0) s_ps[tid >> 5] = v;
    }
    __syncthreads();

    if (tid < N_HALF) {
        // LTP via spike bitmask over smem trace row (complement trick caps work at 16 bits/word)
        unsigned mw[8] = {mA.x, mA.y, mA.z, mA.w, mB.x, mB.y, mB.z, mB.w};
        float ltp = 0.f;
#pragma unroll
        for (int w = 0; w < 8; w++) {
            unsigned m = mw[w];
            int pc = __popc(m);
            const float* base = s_tr + w * 32;
            if (pc == 32) {
                ltp += s_ps[w];
            } else if (pc > 16) {
                unsigned c = ~m;
                float neg = 0.f;
                do {
                    int b = __ffs(c) - 1;
                    c &= c - 1;
                    neg += base[b];
                } while (c);
                ltp += s_ps[w] - neg;
            } else if (m) {
                do {
                    int b = __ffs(m) - 1;
                    m &= m - 1;
                    ltp += base[b];
                } while (m);
            }
        }

        // LTD via img-active list: int4 index loads + 4 independent accumulators
        const int* lst = &g_imglist[k * B_SZ];
        float d0 = 0.f, d1 = 0.f, d2 = 0.f, d3 = 0.f;
        int i = 0;
        for (; i + 4 <= icnt; i += 4) {
            int4 b4 = *reinterpret_cast<const int4*>(lst + i);
            d0 += g_post[b4.x * N_SZ + n];
            d1 += g_post[b4.y * N_SZ + n];
            d2 += g_post[b4.z * N_SZ + n];
            d3 += g_post[b4.w * N_SZ + n];
        }
        for (; i < icnt; i++) d0 += g_post[lst[i] * N_SZ + n];
        float ltd = (d0 + d1) + (d2 + d3);

        wv = wv + A_PLUS * ltp - A_MINUS * ltd;
        wv = fminf(fmaxf(wv, 0.f), 1.f);
        g_Wt[k * N_SZ + n] = wv;
    }
}

// ---------------- final: transpose Wt back into output layout [N, IN] ----------------
__global__ void k_write_w(float* __restrict__ outW) {
    int idx = blockIdx.x * blockDim.x + threadIdx.x;
    if (idx >= N_SZ * IN_SZ) return;
    int n = idx / IN_SZ, k = idx % IN_SZ;
    outW[idx] = g_Wt[k * N_SZ + n];
}

// ---------------- launch ----------------
extern "C" void kernel_launch(void* const* d_in, const int* in_sizes, int n_in,
                              void* d_out, int out_size) {
    const float* img = (const float*)d_in[0];
    const float* W   = (const float*)d_in[1];
    if (n_in >= 2 && in_sizes[0] == N_SZ * IN_SZ) {
        const float* tmp = img; img = W; W = tmp;
    }

    float* out = (float*)d_out;
    float* memrec = out;
    float* spkrec = out + (size_t)T_STEPS * B_SZ * N_SZ;
    float* outW   = out + 2 * (size_t)T_STEPS * B_SZ * N_SZ;

    k_init<<<256, 256>>>(W);

    dim3 gridN(B_SZ, 2);
    dim3 gridS(IN_SZ, 2);
    for (int t = 0; t < T_STEPS; t++) {
        k_neuron<<<gridN, 256>>>(img, t, memrec, spkrec);
        k_prep<<<PREP_TOT, 256>>>(img, spkrec, t);
        k_stdp<<<gridS, 256>>>();
    }
    k_write_w<<<(N_SZ * IN_SZ + 255) / 256, 256>>>(outW);
}

// round 12
// speedup vs baseline: 1.0156x; 1.0156x over previous
#include <cuda_runtime.h>
#include <cstdint>
#include <climits>

#define T_STEPS 200
#define B_SZ    256
#define IN_SZ   784
#define N_SZ    400
#define N_HALF  200

#define ALPHA      0.9f
#define BETA       0.8f
#define THRESH     1.0f
#define BETA_PLUS  0.9f
#define BETA_MINUS 0.9f
#define A_PLUS     1e-3f
#define A_MINUS    1e-3f
#define LI_STR     0.1f

// ---------------- persistent device state ----------------
__device__ float g_Wt[IN_SZ * N_SZ];       // W transposed: Wt[k*N + n] = W[n, k]
__device__ float g_syn[B_SZ * N_SZ];
__device__ float g_mem[B_SZ * N_SZ];
__device__ float g_post[B_SZ * N_SZ];
__device__ float g_trT[IN_SZ * B_SZ];      // TRANSPOSED pre-trace: trT[k*B + b] = tr_t[b,k]
__device__ int   g_win[T_STEPS * B_SZ];    // per (t,b) winner via atomicMin
__device__ int   g_flag[T_STEPS];
__device__ int   g_imgcnt[IN_SZ];
__device__ __align__(16) int g_imglist[IN_SZ * B_SZ];  // per input k: batch rows with img=1
__device__ __align__(16) unsigned g_spkmask[N_SZ * 8]; // per neuron n: 256-bit spike mask over b

// ---------------- init ----------------
__global__ void k_init(const float* __restrict__ W) {
    int idx = blockIdx.x * blockDim.x + threadIdx.x;
    int stride = gridDim.x * blockDim.x;
    for (int j = idx; j < IN_SZ * N_SZ; j += stride) {
        int k = j / N_SZ, n = j % N_SZ;
        g_Wt[j] = W[n * IN_SZ + k];
    }
    for (int j = idx; j < B_SZ * N_SZ; j += stride) {
        g_syn[j] = 0.f; g_mem[j] = 0.f; g_post[j] = 0.f;
    }
    for (int j = idx; j < IN_SZ * B_SZ; j += stride) g_trT[j] = 0.f;
    for (int j = idx; j < T_STEPS * B_SZ; j += stride) g_win[j] = INT_MAX;
    for (int j = idx; j < T_STEPS; j += stride) g_flag[j] = 0;
}

// ---------------- K1: neuron update, grid (B, 2): one block per (batch row, n-half) ----
__global__ void __launch_bounds__(256) k_neuron(const float* __restrict__ img, int t,
                                                float* __restrict__ memrec,
                                                float* __restrict__ spkrec) {
    int b = blockIdx.x;
    int half = blockIdx.y;
    int tid = threadIdx.x;

    __shared__ float simg[IN_SZ];
    __shared__ int   s_act[IN_SZ];
    __shared__ int   s_cnt;
    __shared__ int   s_win;
    __shared__ int   s_any;

    const float* imgt = img + ((size_t)t * B_SZ + b) * IN_SZ;
    for (int k = tid; k < IN_SZ; k += 256) simg[k] = imgt[k];
    if (tid == 0) { s_win = INT_MAX; s_any = 0; }
    __syncthreads();

    // warp 0: order-preserving compaction of active input indices
    if (tid < 32) {
        int base = 0;
        for (int c = 0; c < (IN_SZ + 31) / 32; c++) {
            int k = c * 32 + tid;
            bool act = (k < IN_SZ) && (simg[k] != 0.0f);
            unsigned m = __ballot_sync(0xffffffffu, act);
            if (act) s_act[base + __popc(m & ((1u << tid) - 1u))] = k;
            base += __popc(m);
        }
        if (tid == 0) s_cnt = base;
    }
    __syncthreads();

    int cnt = s_cnt;
    if (tid < N_HALF) {
        int n = half * N_HALF + tid;
        // hoist state loads so they overlap the gather
        float m = g_mem[b * N_SZ + n];
        float s = g_syn[b * N_SZ + n];

        // gather with 4 independent accumulators (breaks the FADD latency chain)
        float c0 = 0.f, c1 = 0.f, c2 = 0.f, c3 = 0.f;
        int i = 0;
        for (; i + 4 <= cnt; i += 4) {
            int k0 = s_act[i], k1 = s_act[i + 1], k2 = s_act[i + 2], k3 = s_act[i + 3];
            c0 += g_Wt[k0 * N_SZ + n];
            c1 += g_Wt[k1 * N_SZ + n];
            c2 += g_Wt[k2 * N_SZ + n];
            c3 += g_Wt[k3 * N_SZ + n];
        }
        for (; i < cnt; i++) c0 += g_Wt[s_act[i] * N_SZ + n];
        float cur = (c0 + c1) + (c2 + c3);

        float reset = (m > THRESH) ? 1.0f : 0.0f;
        s = ALPHA * s + cur;
        m = BETA * m + s - reset * THRESH;
        float spk = (m > THRESH) ? 1.0f : 0.0f;

        size_t rec = ((size_t)t * B_SZ + b) * N_SZ + n;
        memrec[rec] = m;
        spkrec[rec] = spk;
        g_syn[b * N_SZ + n] = s;
        g_mem[b * N_SZ + n] = m;

        if (spk != 0.f) { atomicMin(&s_win, n); s_any = 1; }
    }
    __syncthreads();
    if (tid == 0) {
        if (s_win != INT_MAX) atomicMin(&g_win[t * B_SZ + b], s_win);
        if (s_any) atomicOr(&g_flag[t], 1);
    }
}

// ---------------- K2: prep ----------------
// Blocks [0,98):    img-active lists per k (8 warps x 98 = 784)
// Blocks [98,148):  spike bitmasks per n (8 warps x 50 = 400)
// Blocks [148,548): element-wise LI + post-trace update over [B,N]
// Blocks [548,748): transposed trace update trT = bp*trT + img[t-1]^T (32x32 tiles)
#define PREP_IMG  98
#define PREP_MSK  148
#define PREP_LI   548
#define PREP_TOT  748
__global__ void __launch_bounds__(256) k_prep(const float* __restrict__ img,
                                              const float* __restrict__ spkrec, int t) {
    int bid = blockIdx.x;
    int tid = threadIdx.x;

    if (bid < PREP_IMG) {
        int w = tid >> 5, lane = tid & 31;
        int k = bid * 8 + w;
        const float* imgt = img + (size_t)t * B_SZ * IN_SZ;
        int base = 0;
        for (int c = 0; c < B_SZ / 32; c++) {
            int b = c * 32 + lane;
            bool a = imgt[(size_t)b * IN_SZ + k] != 0.0f;
            unsigned m = __ballot_sync(0xffffffffu, a);
            if (a) g_imglist[k * B_SZ + base + __popc(m & ((1u << lane) - 1u))] = b;
            base += __popc(m);
        }
        if (lane == 0) g_imgcnt[k] = base;
    } else if (bid < PREP_MSK) {
        int w = tid >> 5, lane = tid & 31;
        int n = (bid - PREP_IMG) * 8 + w;
        const float* spkt = spkrec + (size_t)t * B_SZ * N_SZ;
        for (int c = 0; c < B_SZ / 32; c++) {
            int b = c * 32 + lane;
            bool a = spkt[b * N_SZ + n] != 0.0f;
            unsigned m = __ballot_sync(0xffffffffu, a);
            if (lane == 0) g_spkmask[n * 8 + c] = m;
        }
    } else if (bid < PREP_LI) {
        int idx = (bid - PREP_MSK) * 256 + tid;
        if (idx < B_SZ * N_SZ) {
            int b = idx / N_SZ, n = idx % N_SZ;
            float spk = spkrec[(size_t)t * B_SZ * N_SZ + idx];
            if (g_flag[t]) {
                int win = g_win[t * B_SZ + b];
                if (win == INT_MAX) win = 0;   // argmax of all-zeros row = 0
                if (n != win) g_syn[idx] -= LI_STR;
            }
            g_post[idx] = BETA_MINUS * g_post[idx] + spk;
        }
    } else {
        if (t == 0) return;   // trT stays zero for step 0
        int d = bid - PREP_LI;             // 0..199
        int kt = d % 25, bt = d / 25;      // 25 k-tiles x 8 b-tiles
        int k0 = kt * 32, b0 = bt * 32;
        __shared__ float s[32][33];
        int tx = tid & 31, ty = tid >> 5;  // ty 0..7
        const float* imgp = img + (size_t)(t - 1) * B_SZ * IN_SZ;
#pragma unroll
        for (int r = 0; r < 4; r++) {
            int bl = ty + r * 8;           // local b
            int k = k0 + tx;
            s[bl][tx] = (k < IN_SZ) ? imgp[(size_t)(b0 + bl) * IN_SZ + k] : 0.f;
        }
        __syncthreads();
#pragma unroll
        for (int r = 0; r < 4; r++) {
            int kl = ty + r * 8;           // local k
            int k = k0 + kl;
            if (k < IN_SZ) {
                int j = k * B_SZ + b0 + tx;
                g_trT[j] = BETA_PLUS * g_trT[j] + s[tx][kl];
            }
        }
    }
}

// ---------------- K3: fused STDP update, grid (392, 2): 2 k-values x n-half per block --
// Wt[k,n] = clip(Wt[k,n] + A_PLUS * sum_{b: spk[b,n]=1} trT[k,b]
//                        - A_MINUS * sum_{b: img[b,k]=1} post[b,n], 0, 1)
__global__ void __launch_bounds__(256) k_stdp() {
    int k0 = blockIdx.x * 2;
    int half = blockIdx.y;
    int tid = threadIdx.x;
    int n = half * N_HALF + tid;

    __shared__ __align__(16) float s_tr2[B_SZ * 2];  // interleaved: [2b+kk] = trT[k0+kk, b]
    __shared__ float s_ps2[8][2];                    // per-word partial sums, per k

    // issue all independent loads up front
    uint4 mA = make_uint4(0, 0, 0, 0), mB = make_uint4(0, 0, 0, 0);
    float wv0 = 0.f, wv1 = 0.f;
    if (tid < N_HALF) {
        const uint4* mp = reinterpret_cast<const uint4*>(&g_spkmask[n * 8]);
        mA = mp[0]; mB = mp[1];
        wv0 = g_Wt[k0 * N_SZ + n];
        wv1 = g_Wt[(k0 + 1) * N_SZ + n];
    }
    int icnt0 = g_imgcnt[k0];       // warp-uniform broadcast loads
    int icnt1 = g_imgcnt[k0 + 1];

    // all 8 warps: load both trace rows + deterministic per-chunk reductions
    {
        float trv0 = g_trT[k0 * B_SZ + tid];
        float trv1 = g_trT[(k0 + 1) * B_SZ + tid];
        s_tr2[2 * tid]     = trv0;
        s_tr2[2 * tid + 1] = trv1;
        float v0 = trv0, v1 = trv1;
#pragma unroll
        for (int off = 16; off > 0; off >>= 1) {
            v0 += __shfl_xor_sync(0xffffffffu, v0, off);
            v1 += __shfl_xor_sync(0xffffffffu, v1, off);
        }
        if ((tid & 31) == 0) { s_ps2[tid >> 5][0] = v0; s_ps2[tid >> 5][1] = v1; }
    }
    __syncthreads();

    if (tid < N_HALF) {
        // LTP via spike bitmask; each set bit yields a float2 (both k) from smem
        unsigned mw[8] = {mA.x, mA.y, mA.z, mA.w, mB.x, mB.y, mB.z, mB.w};
        float ltp0 = 0.f, ltp1 = 0.f;
#pragma unroll
        for (int w = 0; w < 8; w++) {
            unsigned m = mw[w];
            int pc = __popc(m);
            const float2* base = reinterpret_cast<const float2*>(s_tr2) + w * 32;
            if (pc == 32) {
                ltp0 += s_ps2[w][0];
                ltp1 += s_ps2[w][1];
            } else if (pc > 16) {
                unsigned c = ~m;
                float n0 = 0.f, n1 = 0.f;
                do {
                    int b = __ffs(c) - 1;
                    c &= c - 1;
                    float2 v = base[b];
                    n0 += v.x; n1 += v.y;
                } while (c);
                ltp0 += s_ps2[w][0] - n0;
                ltp1 += s_ps2[w][1] - n1;
            } else if (m) {
                do {
                    int b = __ffs(m) - 1;
                    m &= m - 1;
                    float2 v = base[b];
                    ltp0 += v.x; ltp1 += v.y;
                } while (m);
            }
        }

        // LTD via img-active lists (one per k): int4 index loads + indep accumulators
        const float* postn = g_post + n;
        float ltd0, ltd1;
        {
            const int* lst = &g_imglist[k0 * B_SZ];
            float d0 = 0.f, d1 = 0.f, d2 = 0.f, d3 = 0.f;
            int i = 0;
            for (; i + 4 <= icnt0; i += 4) {
                int4 b4 = *reinterpret_cast<const int4*>(lst + i);
                d0 += postn[b4.x * N_SZ];
                d1 += postn[b4.y * N_SZ];
                d2 += postn[b4.z * N_SZ];
                d3 += postn[b4.w * N_SZ];
            }
            for (; i < icnt0; i++) d0 += postn[lst[i] * N_SZ];
            ltd0 = (d0 + d1) + (d2 + d3);
        }
        {
            const int* lst = &g_imglist[(k0 + 1) * B_SZ];
            float d0 = 0.f, d1 = 0.f, d2 = 0.f, d3 = 0.f;
            int i = 0;
            for (; i + 4 <= icnt1; i += 4) {
                int4 b4 = *reinterpret_cast<const int4*>(lst + i);
                d0 += postn[b4.x * N_SZ];
                d1 += postn[b4.y * N_SZ];
                d2 += postn[b4.z * N_SZ];
                d3 += postn[b4.w * N_SZ];
            }
            for (; i < icnt1; i++) d0 += postn[lst[i] * N_SZ];
            ltd1 = (d0 + d1) + (d2 + d3);
        }

        wv0 = wv0 + A_PLUS * ltp0 - A_MINUS * ltd0;
        wv1 = wv1 + A_PLUS * ltp1 - A_MINUS * ltd1;
        wv0 = fminf(fmaxf(wv0, 0.f), 1.f);
        wv1 = fminf(fmaxf(wv1, 0.f), 1.f);
        g_Wt[k0 * N_SZ + n] = wv0;
        g_Wt[(k0 + 1) * N_SZ + n] = wv1;
    }
}

// ---------------- final: transpose Wt back into output layout [N, IN] ----------------
__global__ void k_write_w(float* __restrict__ outW) {
    int idx = blockIdx.x * blockDim.x + threadIdx.x;
    if (idx >= N_SZ * IN_SZ) return;
    int n = idx / IN_SZ, k = idx % IN_SZ;
    outW[idx] = g_Wt[k * N_SZ + n];
}

// ---------------- launch ----------------
extern "C" void kernel_launch(void* const* d_in, const int* in_sizes, int n_in,
                              void* d_out, int out_size) {
    const float* img = (const float*)d_in[0];
    const float* W   = (const float*)d_in[1];
    if (n_in >= 2 && in_sizes[0] == N_SZ * IN_SZ) {
        const float* tmp = img; img = W; W = tmp;
    }

    float* out = (float*)d_out;
    float* memrec = out;
    float* spkrec = out + (size_t)T_STEPS * B_SZ * N_SZ;
    float* outW   = out + 2 * (size_t)T_STEPS * B_SZ * N_SZ;

    k_init<<<256, 256>>>(W);

    dim3 gridN(B_SZ, 2);
    dim3 gridS(IN_SZ / 2, 2);
    for (int t = 0; t < T_STEPS; t++) {
        k_neuron<<<gridN, 256>>>(img, t, memrec, spkrec);
        k_prep<<<PREP_TOT, 256>>>(img, spkrec, t);
        k_stdp<<<gridS, 256>>>();
    }
    k_write_w<<<(N_SZ * IN_SZ + 255) / 256, 256>>>(outW);
}

// round 13
// speedup vs baseline: 1.1798x; 1.1617x over previous
#include <cuda_runtime.h>
#include <cstdint>
#include <climits>

#define T_STEPS 200
#define B_SZ    256
#define IN_SZ   784
#define N_SZ    400
#define N_HALF  200

#define ALPHA      0.9f
#define BETA       0.8f
#define THRESH     1.0f
#define BETA_PLUS  0.9f
#define BETA_MINUS 0.9f
#define A_PLUS     1e-3f
#define A_MINUS    1e-3f
#define LI_STR     0.1f

// block-range split for the fused neuron kernel
#define NEU_BLKS  512                 // 256 b x 2 n-halves
#define TRT_BLKS  200                 // 25 k-tiles x 8 b-tiles
#define IMG_BLKS  98                  // 98 x 8 warps = 784 k
#define FUSE_TOT  (NEU_BLKS + TRT_BLKS + IMG_BLKS)

// ---------------- persistent device state ----------------
__device__ float g_Wt[IN_SZ * N_SZ];       // W transposed: Wt[k*N + n] = W[n, k]
__device__ float g_syn[B_SZ * N_SZ];       // stored PRE-lateral-inhibition (LI applied lazily)
__device__ float g_mem[B_SZ * N_SZ];
__device__ float g_post[B_SZ * N_SZ];
__device__ float g_trT[IN_SZ * B_SZ];      // TRANSPOSED pre-trace: trT[k*B + b] = tr_t[b,k]
__device__ int   g_win[T_STEPS * B_SZ];    // per (t,b) winner via atomicMin (init INT_MAX)
__device__ int   g_flag[T_STEPS];
__device__ int   g_imgcnt[IN_SZ];
__device__ __align__(16) int g_imglist[IN_SZ * B_SZ];     // per input k: batch rows with img=1
__device__ __align__(16) unsigned g_spkmask[2][N_SZ * 8]; // double-buffered 256-bit spike masks

// ---------------- init ----------------
__global__ void k_init(const float* __restrict__ W) {
    int idx = blockIdx.x * blockDim.x + threadIdx.x;
    int stride = gridDim.x * blockDim.x;
    for (int j = idx; j < IN_SZ * N_SZ; j += stride) {
        int k = j / N_SZ, n = j % N_SZ;
        g_Wt[j] = W[n * IN_SZ + k];
    }
    for (int j = idx; j < B_SZ * N_SZ; j += stride) {
        g_syn[j] = 0.f; g_mem[j] = 0.f; g_post[j] = 0.f;
    }
    for (int j = idx; j < IN_SZ * B_SZ; j += stride) g_trT[j] = 0.f;
    for (int j = idx; j < T_STEPS * B_SZ; j += stride) g_win[j] = INT_MAX;
    for (int j = idx; j < T_STEPS; j += stride) g_flag[j] = 0;
    for (int j = idx; j < 2 * N_SZ * 8; j += stride) g_spkmask[0][j] = 0u;  // both buffers
}

// ---------------- K1: fused neuron + trT update + imglist ----------------
// Blocks [0,512):    neuron update for (b = bid>>1, n-half = bid&1)
//                    fuses: lazy LI from t-1, dynamics, records, post update,
//                    spike-mask atomicOr into buffer t&1, winner/flag
// Blocks [512,712):  trT = bp*trT + img[t-1]^T (32x32 transpose tiles)
// Blocks [712,810):  img-active lists per k for step t (8 warps x 98 = 784)
__global__ void __launch_bounds__(256) k_neuron(const float* __restrict__ img, int t,
                                                float* __restrict__ memrec,
                                                float* __restrict__ spkrec) {
    int bid = blockIdx.x;
    int tid = threadIdx.x;

    if (bid < NEU_BLKS) {
        int b = bid >> 1;
        int half = bid & 1;

        __shared__ float simg[IN_SZ];
        __shared__ int   s_act[IN_SZ];
        __shared__ int   s_cnt;
        __shared__ int   s_win;
        __shared__ int   s_any;

        const float* imgt = img + ((size_t)t * B_SZ + b) * IN_SZ;
        for (int k = tid; k < IN_SZ; k += 256) simg[k] = imgt[k];
        if (tid == 0) { s_win = INT_MAX; s_any = 0; }
        __syncthreads();

        // warp 0: order-preserving compaction of active input indices
        if (tid < 32) {
            int base = 0;
            for (int c = 0; c < (IN_SZ + 31) / 32; c++) {
                int k = c * 32 + tid;
                bool act = (k < IN_SZ) && (simg[k] != 0.0f);
                unsigned m = __ballot_sync(0xffffffffu, act);
                if (act) s_act[base + __popc(m & ((1u << tid) - 1u))] = k;
                base += __popc(m);
            }
            if (tid == 0) s_cnt = base;
        }
        __syncthreads();

        int cnt = s_cnt;
        if (tid < N_HALF) {
            int n = half * N_HALF + tid;
            // hoist state loads so they overlap the gather
            float m = g_mem[b * N_SZ + n];
            float s = g_syn[b * N_SZ + n];
            float po = g_post[b * N_SZ + n];

            // lazy lateral inhibition from the previous step
            if (t > 0 && g_flag[t - 1]) {
                int win = g_win[(t - 1) * B_SZ + b];
                if (win == INT_MAX) win = 0;
                if (n != win) s -= LI_STR;
            }

            // gather with 4 independent accumulators
            float c0 = 0.f, c1 = 0.f, c2 = 0.f, c3 = 0.f;
            int i = 0;
            for (; i + 4 <= cnt; i += 4) {
                int k0 = s_act[i], k1 = s_act[i + 1], k2 = s_act[i + 2], k3 = s_act[i + 3];
                c0 += g_Wt[k0 * N_SZ + n];
                c1 += g_Wt[k1 * N_SZ + n];
                c2 += g_Wt[k2 * N_SZ + n];
                c3 += g_Wt[k3 * N_SZ + n];
            }
            for (; i < cnt; i++) c0 += g_Wt[s_act[i] * N_SZ + n];
            float cur = (c0 + c1) + (c2 + c3);

            float reset = (m > THRESH) ? 1.0f : 0.0f;
            s = ALPHA * s + cur;
            m = BETA * m + s - reset * THRESH;
            float spk = (m > THRESH) ? 1.0f : 0.0f;

            size_t rec = ((size_t)t * B_SZ + b) * N_SZ + n;
            memrec[rec] = m;
            spkrec[rec] = spk;
            g_syn[b * N_SZ + n] = s;     // pre-LI; LI applied at t+1
            g_mem[b * N_SZ + n] = m;
            g_post[b * N_SZ + n] = BETA_MINUS * po + spk;

            if (spk != 0.f) {
                atomicMin(&s_win, n);
                s_any = 1;
                atomicOr(&g_spkmask[t & 1][n * 8 + (b >> 5)], 1u << (b & 31));
            }
        }
        __syncthreads();
        if (tid == 0) {
            if (s_win != INT_MAX) atomicMin(&g_win[t * B_SZ + b], s_win);
            if (s_any) atomicOr(&g_flag[t], 1);
        }
    } else if (bid < NEU_BLKS + TRT_BLKS) {
        if (t == 0) return;   // trT stays zero for step 0
        int d = bid - NEU_BLKS;            // 0..199
        int kt = d % 25, bt = d / 25;      // 25 k-tiles x 8 b-tiles
        int k0 = kt * 32, b0 = bt * 32;
        __shared__ float s[32][33];
        int tx = tid & 31, ty = tid >> 5;  // ty 0..7
        const float* imgp = img + (size_t)(t - 1) * B_SZ * IN_SZ;
#pragma unroll
        for (int r = 0; r < 4; r++) {
            int bl = ty + r * 8;           // local b
            int k = k0 + tx;
            s[bl][tx] = (k < IN_SZ) ? imgp[(size_t)(b0 + bl) * IN_SZ + k] : 0.f;
        }
        __syncthreads();
#pragma unroll
        for (int r = 0; r < 4; r++) {
            int kl = ty + r * 8;           // local k
            int k = k0 + kl;
            if (k < IN_SZ) {
                int j = k * B_SZ + b0 + tx;
                g_trT[j] = BETA_PLUS * g_trT[j] + s[tx][kl];
            }
        }
    } else {
        int w = tid >> 5, lane = tid & 31;
        int k = (bid - NEU_BLKS - TRT_BLKS) * 8 + w;   // 98*8 = 784
        const float* imgt = img + (size_t)t * B_SZ * IN_SZ;
        int base = 0;
        for (int c = 0; c < B_SZ / 32; c++) {
            int b = c * 32 + lane;
            bool a = imgt[(size_t)b * IN_SZ + k] != 0.0f;
            unsigned m = __ballot_sync(0xffffffffu, a);
            if (a) g_imglist[k * B_SZ + base + __popc(m & ((1u << lane) - 1u))] = b;
            base += __popc(m);
        }
        if (lane == 0) g_imgcnt[k] = base;
    }
}

// ---------------- K2: fused STDP update, grid (392, 2): 2 k-values x n-half ----------
// Also zeroes the OTHER spike-mask buffer (for step t+1) using blocks x<100, y==0.
__global__ void __launch_bounds__(256) k_stdp(int par) {
    int k0 = blockIdx.x * 2;
    int half = blockIdx.y;
    int tid = threadIdx.x;
    int n = half * N_HALF + tid;

    // zero next step's mask buffer (different buffer than the one read below -> no race)
    if (half == 0 && blockIdx.x < 100 && tid < 32) {
        g_spkmask[par ^ 1][blockIdx.x * 32 + tid] = 0u;
    }

    __shared__ __align__(16) float s_tr2[B_SZ * 2];  // interleaved: [2b+kk] = trT[k0+kk, b]
    __shared__ float s_ps2[8][2];                    // per-word partial sums, per k

    // issue all independent loads up front
    uint4 mA = make_uint4(0, 0, 0, 0), mB = make_uint4(0, 0, 0, 0);
    float wv0 = 0.f, wv1 = 0.f;
    if (tid < N_HALF) {
        const uint4* mp = reinterpret_cast<const uint4*>(&g_spkmask[par][n * 8]);
        mA = mp[0]; mB = mp[1];
        wv0 = g_Wt[k0 * N_SZ + n];
        wv1 = g_Wt[(k0 + 1) * N_SZ + n];
    }
    int icnt0 = g_imgcnt[k0];       // warp-uniform broadcast loads
    int icnt1 = g_imgcnt[k0 + 1];

    // all 8 warps: load both trace rows + deterministic per-chunk reductions
    {
        float trv0 = g_trT[k0 * B_SZ + tid];
        float trv1 = g_trT[(k0 + 1) * B_SZ + tid];
        s_tr2[2 * tid]     = trv0;
        s_tr2[2 * tid + 1] = trv1;
        float v0 = trv0, v1 = trv1;
#pragma unroll
        for (int off = 16; off > 0; off >>= 1) {
            v0 += __shfl_xor_sync(0xffffffffu, v0, off);
            v1 += __shfl_xor_sync(0xffffffffu, v1, off);
        }
        if ((tid & 31) == 0) { s_ps2[tid >> 5][0] = v0; s_ps2[tid >> 5][1] = v1; }
    }
    __syncthreads();

    if (tid < N_HALF) {
        // LTP via spike bitmask; each set bit yields a float2 (both k) from smem
        unsigned mw[8] = {mA.x, mA.y, mA.z, mA.w, mB.x, mB.y, mB.z, mB.w};
        float ltp0 = 0.f, ltp1 = 0.f;
#pragma unroll
        for (int w = 0; w < 8; w++) {
            unsigned m = mw[w];
            int pc = __popc(m);
            const float2* base = reinterpret_cast<const float2*>(s_tr2) + w * 32;
            if (pc == 32) {
                ltp0 += s_ps2[w][0];
                ltp1 += s_ps2[w][1];
            } else if (pc > 16) {
                unsigned c = ~m;
                float n0 = 0.f, n1 = 0.f;
                do {
                    int b = __ffs(c) - 1;
                    c &= c - 1;
                    float2 v = base[b];
                    n0 += v.x; n1 += v.y;
                } while (c);
                ltp0 += s_ps2[w][0] - n0;
                ltp1 += s_ps2[w][1] - n1;
            } else if (m) {
                do {
                    int b = __ffs(m) - 1;
                    m &= m - 1;
                    float2 v = base[b];
                    ltp0 += v.x; ltp1 += v.y;
                } while (m);
            }
        }

        // LTD via img-active lists (one per k): int4 index loads + indep accumulators
        const float* postn = g_post + n;
        float ltd0, ltd1;
        {
            const int* lst = &g_imglist[k0 * B_SZ];
            float d0 = 0.f, d1 = 0.f, d2 = 0.f, d3 = 0.f;
            int i = 0;
            for (; i + 4 <= icnt0; i += 4) {
                int4 b4 = *reinterpret_cast<const int4*>(lst + i);
                d0 += postn[b4.x * N_SZ];
                d1 += postn[b4.y * N_SZ];
                d2 += postn[b4.z * N_SZ];
                d3 += postn[b4.w * N_SZ];
            }
            for (; i < icnt0; i++) d0 += postn[lst[i] * N_SZ];
            ltd0 = (d0 + d1) + (d2 + d3);
        }
        {
            const int* lst = &g_imglist[(k0 + 1) * B_SZ];
            float d0 = 0.f, d1 = 0.f, d2 = 0.f, d3 = 0.f;
            int i = 0;
            for (; i + 4 <= icnt1; i += 4) {
                int4 b4 = *reinterpret_cast<const int4*>(lst + i);
                d0 += postn[b4.x * N_SZ];
                d1 += postn[b4.y * N_SZ];
                d2 += postn[b4.z * N_SZ];
                d3 += postn[b4.w * N_SZ];
            }
            for (; i < icnt1; i++) d0 += postn[lst[i] * N_SZ];
            ltd1 = (d0 + d1) + (d2 + d3);
        }

        wv0 = wv0 + A_PLUS * ltp0 - A_MINUS * ltd0;
        wv1 = wv1 + A_PLUS * ltp1 - A_MINUS * ltd1;
        wv0 = fminf(fmaxf(wv0, 0.f), 1.f);
        wv1 = fminf(fmaxf(wv1, 0.f), 1.f);
        g_Wt[k0 * N_SZ + n] = wv0;
        g_Wt[(k0 + 1) * N_SZ + n] = wv1;
    }
}

// ---------------- final: transpose Wt back into output layout [N, IN] ----------------
__global__ void k_write_w(float* __restrict__ outW) {
    int idx = blockIdx.x * blockDim.x + threadIdx.x;
    if (idx >= N_SZ * IN_SZ) return;
    int n = idx / IN_SZ, k = idx % IN_SZ;
    outW[idx] = g_Wt[k * N_SZ + n];
}

// ---------------- launch ----------------
extern "C" void kernel_launch(void* const* d_in, const int* in_sizes, int n_in,
                              void* d_out, int out_size) {
    const float* img = (const float*)d_in[0];
    const float* W   = (const float*)d_in[1];
    if (n_in >= 2 && in_sizes[0] == N_SZ * IN_SZ) {
        const float* tmp = img; img = W; W = tmp;
    }

    float* out = (float*)d_out;
    float* memrec = out;
    float* spkrec = out + (size_t)T_STEPS * B_SZ * N_SZ;
    float* outW   = out + 2 * (size_t)T_STEPS * B_SZ * N_SZ;

    k_init<<<256, 256>>>(W);

    dim3 gridS(IN_SZ / 2, 2);
    for (int t = 0; t < T_STEPS; t++) {
        k_neuron<<<FUSE_TOT, 256>>>(img, t, memrec, spkrec);
        k_stdp<<<gridS, 256>>>(t & 1);
    }
    k_write_w<<<(N_SZ * IN_SZ + 255) / 256, 256>>>(outW);
}

// round 15
// speedup vs baseline: 1.2288x; 1.0415x over previous
#include <cuda_runtime.h>
#include <cstdint>
#include <climits>

#define T_STEPS 200
#define B_SZ    256
#define IN_SZ   784
#define N_SZ    400
#define N_HALF  200

#define ALPHA      0.9f
#define BETA       0.8f
#define THRESH     1.0f
#define BETA_PLUS  0.9f
#define BETA_MINUS 0.9f
#define A_PLUS     1e-3f
#define A_MINUS    1e-3f
#define LI_STR     0.1f

// block-range split for the fused neuron kernel
#define NEU_BLKS  512                 // 256 b x 2 n-halves
#define TRT_BLKS  200                 // 25 k-tiles x 8 b-tiles
#define IMG_BLKS  98                  // 98 x 8 warps = 784 k
#define FUSE_TOT  (NEU_BLKS + TRT_BLKS + IMG_BLKS)

// ---------------- persistent device state ----------------
__device__ float g_Wt[IN_SZ * N_SZ];       // W transposed: Wt[k*N + n] = W[n, k]
__device__ float g_syn[B_SZ * N_SZ];       // stored PRE-lateral-inhibition (LI applied lazily)
__device__ float g_mem[B_SZ * N_SZ];
__device__ float g_post[B_SZ * N_SZ];
__device__ float g_trT[IN_SZ * B_SZ];      // TRANSPOSED pre-trace: trT[k*B + b] = tr_t[b,k]
__device__ int   g_win[T_STEPS * B_SZ];    // per (t,b) winner via atomicMin (init INT_MAX)
__device__ int   g_flag[T_STEPS];
__device__ int   g_imgcnt[IN_SZ];
__device__ __align__(16) int g_imglist[IN_SZ * B_SZ];     // per input k: batch rows with img=1
__device__ __align__(16) unsigned g_spkmask[2][N_SZ * 8]; // double-buffered 256-bit spike masks

// ---------------- init ----------------
__global__ void k_init(const float* __restrict__ W) {
    int idx = blockIdx.x * blockDim.x + threadIdx.x;
    int stride = gridDim.x * blockDim.x;
    for (int j = idx; j < IN_SZ * N_SZ; j += stride) {
        int k = j / N_SZ, n = j % N_SZ;
        g_Wt[j] = W[n * IN_SZ + k];
    }
    for (int j = idx; j < B_SZ * N_SZ; j += stride) {
        g_syn[j] = 0.f; g_mem[j] = 0.f; g_post[j] = 0.f;
    }
    for (int j = idx; j < IN_SZ * B_SZ; j += stride) g_trT[j] = 0.f;
    for (int j = idx; j < T_STEPS * B_SZ; j += stride) g_win[j] = INT_MAX;
    for (int j = idx; j < T_STEPS; j += stride) g_flag[j] = 0;
    for (int j = idx; j < 2 * N_SZ * 8; j += stride) g_spkmask[0][j] = 0u;  // both buffers
}

// ---------------- K1: fused neuron + trT update + imglist ----------------
__global__ void __launch_bounds__(256) k_neuron(const float* __restrict__ img, int t,
                                                float* __restrict__ memrec,
                                                float* __restrict__ spkrec) {
    int bid = blockIdx.x;
    int tid = threadIdx.x;

    if (bid < NEU_BLKS) {
        int b = bid >> 1;
        int half = bid & 1;
        int w = tid >> 5, lane = tid & 31;

        __shared__ unsigned s_mask[25];
        __shared__ int s_off[25];
        __shared__ int s_act[IN_SZ];
        __shared__ int s_cnt;
        __shared__ int s_win;
        __shared__ int s_any;

        const float* imgt = img + ((size_t)t * B_SZ + b) * IN_SZ;
        // parallel ballot compaction: warp w covers chunks w, 8+w, 16+w;
        // warp 0 additionally covers the 16-element tail chunk 24 (k in [768,784)).
        float v0 = imgt[tid];
        float v1 = imgt[tid + 256];
        float v2 = (tid + 512 < IN_SZ) ? imgt[tid + 512] : 0.f;
        bool a0 = v0 != 0.f, a1 = v1 != 0.f, a2 = v2 != 0.f;
        unsigned m0 = __ballot_sync(0xffffffffu, a0);
        unsigned m1 = __ballot_sync(0xffffffffu, a1);
        unsigned m2 = __ballot_sync(0xffffffffu, a2);
        bool a3 = false;
        unsigned m3 = 0;
        if (w == 0) {
            int k3 = 768 + lane;
            a3 = (k3 < IN_SZ) && (imgt[k3] != 0.f);
            m3 = __ballot_sync(0xffffffffu, a3);
        }
        if (lane == 0) {
            s_mask[w] = m0;
            s_mask[8 + w] = m1;
            s_mask[16 + w] = m2;
            if (w == 0) s_mask[24] = m3;
        }
        if (tid == 0) { s_win = INT_MAX; s_any = 0; }
        __syncthreads();

        // warp 0: exclusive prefix scan over the 25 chunk popcounts
        if (w == 0) {
            int c = (lane < 25) ? __popc(s_mask[lane]) : 0;
            int inc = c;
#pragma unroll
            for (int off = 1; off < 32; off <<= 1) {
                int x = __shfl_up_sync(0xffffffffu, inc, off);
                if (lane >= off) inc += x;
            }
            if (lane < 25) s_off[lane] = inc - c;
            if (lane == 24) s_cnt = inc;
        }
        __syncthreads();

        // all warps scatter their chunk indices (ascending-k order preserved)
        {
            unsigned lm = (1u << lane) - 1u;
            if (a0) s_act[s_off[w] + __popc(m0 & lm)] = tid;
            if (a1) s_act[s_off[8 + w] + __popc(m1 & lm)] = tid + 256;
            if (a2) s_act[s_off[16 + w] + __popc(m2 & lm)] = tid + 512;
            if (a3) s_act[s_off[24] + __popc(m3 & lm)] = 768 + lane;
        }
        __syncthreads();

        int cnt = s_cnt;
        if (tid < N_HALF) {
            int n = half * N_HALF + tid;
            // hoist state loads so they overlap the gather
            float m = g_mem[b * N_SZ + n];
            float s = g_syn[b * N_SZ + n];
            float po = g_post[b * N_SZ + n];

            // lazy lateral inhibition from the previous step
            if (t > 0 && g_flag[t - 1]) {
                int win = g_win[(t - 1) * B_SZ + b];
                if (win == INT_MAX) win = 0;
                if (n != win) s -= LI_STR;
            }

            // gather with 8 independent accumulators
            float c0 = 0.f, c1 = 0.f, c2 = 0.f, c3 = 0.f;
            float c4 = 0.f, c5 = 0.f, c6 = 0.f, c7 = 0.f;
            int i = 0;
            for (; i + 8 <= cnt; i += 8) {
                c0 += g_Wt[s_act[i]     * N_SZ + n];
                c1 += g_Wt[s_act[i + 1] * N_SZ + n];
                c2 += g_Wt[s_act[i + 2] * N_SZ + n];
                c3 += g_Wt[s_act[i + 3] * N_SZ + n];
                c4 += g_Wt[s_act[i + 4] * N_SZ + n];
                c5 += g_Wt[s_act[i + 5] * N_SZ + n];
                c6 += g_Wt[s_act[i + 6] * N_SZ + n];
                c7 += g_Wt[s_act[i + 7] * N_SZ + n];
            }
            for (; i < cnt; i++) c0 += g_Wt[s_act[i] * N_SZ + n];
            float cur = ((c0 + c1) + (c2 + c3)) + ((c4 + c5) + (c6 + c7));

            float reset = (m > THRESH) ? 1.0f : 0.0f;
            s = ALPHA * s + cur;
            m = BETA * m + s - reset * THRESH;
            float spk = (m > THRESH) ? 1.0f : 0.0f;

            size_t rec = ((size_t)t * B_SZ + b) * N_SZ + n;
            memrec[rec] = m;
            spkrec[rec] = spk;
            g_syn[b * N_SZ + n] = s;     // pre-LI; LI applied at t+1
            g_mem[b * N_SZ + n] = m;
            g_post[b * N_SZ + n] = BETA_MINUS * po + spk;

            if (spk != 0.f) {
                atomicMin(&s_win, n);
                s_any = 1;
                atomicOr(&g_spkmask[t & 1][n * 8 + (b >> 5)], 1u << (b & 31));
            }
        }
        __syncthreads();
        if (tid == 0) {
            if (s_win != INT_MAX) atomicMin(&g_win[t * B_SZ + b], s_win);
            if (s_any) atomicOr(&g_flag[t], 1);
        }
    } else if (bid < NEU_BLKS + TRT_BLKS) {
        if (t == 0) return;   // trT stays zero for step 0
        int d = bid - NEU_BLKS;            // 0..199
        int kt = d % 25, bt = d / 25;      // 25 k-tiles x 8 b-tiles
        int k0 = kt * 32, b0 = bt * 32;
        __shared__ float s[32][33];
        int tx = tid & 31, ty = tid >> 5;  // ty 0..7
        const float* imgp = img + (size_t)(t - 1) * B_SZ * IN_SZ;
#pragma unroll
        for (int r = 0; r < 4; r++) {
            int bl = ty + r * 8;           // local b
            int k = k0 + tx;
            s[bl][tx] = (k < IN_SZ) ? imgp[(size_t)(b0 + bl) * IN_SZ + k] : 0.f;
        }
        __syncthreads();
#pragma unroll
        for (int r = 0; r < 4; r++) {
            int kl = ty + r * 8;           // local k
            int k = k0 + kl;
            if (k < IN_SZ) {
                int j = k * B_SZ + b0 + tx;
                g_trT[j] = BETA_PLUS * g_trT[j] + s[tx][kl];
            }
        }
    } else {
        int w = tid >> 5, lane = tid & 31;
        int k = (bid - NEU_BLKS - TRT_BLKS) * 8 + w;   // 98*8 = 784
        const float* imgt = img + (size_t)t * B_SZ * IN_SZ;
        int base = 0;
        for (int c = 0; c < B_SZ / 32; c++) {
            int b = c * 32 + lane;
            bool a = imgt[(size_t)b * IN_SZ + k] != 0.0f;
            unsigned m = __ballot_sync(0xffffffffu, a);
            if (a) g_imglist[k * B_SZ + base + __popc(m & ((1u << lane) - 1u))] = b;
            base += __popc(m);
        }
        if (lane == 0) g_imgcnt[k] = base;
    }
}

// ---------------- K2: fused STDP update, grid (392, 2): 2 k-values x n-half ----------
// Also zeroes the OTHER spike-mask buffer (for step t+1) using blocks x<100, y==0.
__global__ void __launch_bounds__(256) k_stdp(int par) {
    int k0 = blockIdx.x * 2;
    int half = blockIdx.y;
    int tid = threadIdx.x;
    int n = half * N_HALF + tid;

    // zero next step's mask buffer (different buffer than the one read below -> no race)
    if (half == 0 && blockIdx.x < 100 && tid < 32) {
        g_spkmask[par ^ 1][blockIdx.x * 32 + tid] = 0u;
    }

    __shared__ __align__(16) float s_tr2[B_SZ * 2];  // interleaved: [2b+kk] = trT[k0+kk, b]
    __shared__ float s_ps2[8][2];                    // per-word partial sums, per k

    // issue all independent loads up front
    uint4 mA = make_uint4(0, 0, 0, 0), mB = make_uint4(0, 0, 0, 0);
    float wv0 = 0.f, wv1 = 0.f;
    if (tid < N_HALF) {
        const uint4* mp = reinterpret_cast<const uint4*>(&g_spkmask[par][n * 8]);
        mA = mp[0]; mB = mp[1];
        wv0 = g_Wt[k0 * N_SZ + n];
        wv1 = g_Wt[(k0 + 1) * N_SZ + n];
    }
    int icnt0 = g_imgcnt[k0];       // warp-uniform broadcast loads
    int icnt1 = g_imgcnt[k0 + 1];

    // all 8 warps: load both trace rows + deterministic per-chunk reductions
    {
        float trv0 = g_trT[k0 * B_SZ + tid];
        float trv1 = g_trT[(k0 + 1) * B_SZ + tid];
        s_tr2[2 * tid]     = trv0;
        s_tr2[2 * tid + 1] = trv1;
        float v0 = trv0, v1 = trv1;
#pragma unroll
        for (int off = 16; off > 0; off >>= 1) {
            v0 += __shfl_xor_sync(0xffffffffu, v0, off);
            v1 += __shfl_xor_sync(0xffffffffu, v1, off);
        }
        if ((tid & 31) == 0) { s_ps2[tid >> 5][0] = v0; s_ps2[tid >> 5][1] = v1; }
    }
    __syncthreads();

    if (tid < N_HALF) {
        // LTP via spike bitmask; each set bit yields a float2 (both k) from smem
        unsigned mw[8] = {mA.x, mA.y, mA.z, mA.w, mB.x, mB.y, mB.z, mB.w};
        float ltp0 = 0.f, ltp1 = 0.f;
#pragma unroll
        for (int w = 0; w < 8; w++) {
            unsigned m = mw[w];
            int pc = __popc(m);
            const float2* base = reinterpret_cast<const float2*>(s_tr2) + w * 32;
            if (pc == 32) {
                ltp0 += s_ps2[w][0];
                ltp1 += s_ps2[w][1];
            } else if (pc > 16) {
                unsigned c = ~m;
                float n0 = 0.f, n1 = 0.f;
                do {
                    int b = __ffs(c) - 1;
                    c &= c - 1;
                    float2 v = base[b];
                    n0 += v.x; n1 += v.y;
                } while (c);
                ltp0 += s_ps2[w][0] - n0;
                ltp1 += s_ps2[w][1] - n1;
            } else if (m) {
                do {
                    int b = __ffs(m) - 1;
                    m &= m - 1;
                    float2 v = base[b];
                    ltp0 += v.x; ltp1 += v.y;
                } while (m);
            }
        }

        // LTD via img-active lists (one per k): int4 index loads + indep accumulators
        const float* postn = g_post + n;
        float ltd0, ltd1;
        {
            const int* lst = &g_imglist[k0 * B_SZ];
            float d0 = 0.f, d1 = 0.f, d2 = 0.f, d3 = 0.f;
            int i = 0;
            for (; i + 4 <= icnt0; i += 4) {
                int4 b4 = *reinterpret_cast<const int4*>(lst + i);
                d0 += postn[b4.x * N_SZ];
                d1 += postn[b4.y * N_SZ];
                d2 += postn[b4.z * N_SZ];
                d3 += postn[b4.w * N_SZ];
            }
            for (; i < icnt0; i++) d0 += postn[lst[i] * N_SZ];
            ltd0 = (d0 + d1) + (d2 + d3);
        }
        {
            const int* lst = &g_imglist[(k0 + 1) * B_SZ];
            float d0 = 0.f, d1 = 0.f, d2 = 0.f, d3 = 0.f;
            int i = 0;
            for (; i + 4 <= icnt1; i += 4) {
                int4 b4 = *reinterpret_cast<const int4*>(lst + i);
                d0 += postn[b4.x * N_SZ];
                d1 += postn[b4.y * N_SZ];
                d2 += postn[b4.z * N_SZ];
                d3 += postn[b4.w * N_SZ];
            }
            for (; i < icnt1; i++) d0 += postn[lst[i] * N_SZ];
            ltd1 = (d0 + d1) + (d2 + d3);
        }

        wv0 = wv0 + A_PLUS * ltp0 - A_MINUS * ltd0;
        wv1 = wv1 + A_PLUS * ltp1 - A_MINUS * ltd1;
        wv0 = fminf(fmaxf(wv0, 0.f), 1.f);
        wv1 = fminf(fmaxf(wv1, 0.f), 1.f);
        g_Wt[k0 * N_SZ + n] = wv0;
        g_Wt[(k0 + 1) * N_SZ + n] = wv1;
    }
}

// ---------------- final: transpose Wt back into output layout [N, IN] ----------------
__global__ void k_write_w(float* __restrict__ outW) {
    int idx = blockIdx.x * blockDim.x + threadIdx.x;
    if (idx >= N_SZ * IN_SZ) return;
    int n = idx / IN_SZ, k = idx % IN_SZ;
    outW[idx] = g_Wt[k * N_SZ + n];
}

// ---------------- launch ----------------
extern "C" void kernel_launch(void* const* d_in, const int* in_sizes, int n_in,
                              void* d_out, int out_size) {
    const float* img = (const float*)d_in[0];
    const float* W   = (const float*)d_in[1];
    if (n_in >= 2 && in_sizes[0] == N_SZ * IN_SZ) {
        const float* tmp = img; img = W; W = tmp;
    }

    float* out = (float*)d_out;
    float* memrec = out;
    float* spkrec = out + (size_t)T_STEPS * B_SZ * N_SZ;
    float* outW   = out + 2 * (size_t)T_STEPS * B_SZ * N_SZ;

    k_init<<<256, 256>>>(W);

    dim3 gridS(IN_SZ / 2, 2);
    for (int t = 0; t < T_STEPS; t++) {
        k_neuron<<<FUSE_TOT, 256>>>(img, t, memrec, spkrec);
        k_stdp<<<gridS, 256>>>(t & 1);
    }
    k_write_w<<<(N_SZ * IN_SZ + 255) / 256, 256>>>(outW);
}